// round 1
// baseline (speedup 1.0000x reference)
#include <cuda_runtime.h>
#include <math.h>

#define NROWS 8192
#define DDIM  64
#define MARGIN 1.1f
#define EPS 1e-8f

// Scratch: normalized vectors + global accumulator (no allocs allowed).
__device__ float  g_xn[NROWS * DDIM];
__device__ double g_accum;

// ---------------------------------------------------------------------------
// Zero the accumulator (must happen every launch; graph replays reuse state).
// ---------------------------------------------------------------------------
__global__ void zero_kernel() { g_accum = 0.0; }

// ---------------------------------------------------------------------------
// Normalize: one warp per row, 2 elements per lane, warp shuffle reduction.
// xn = x / max(||x||, EPS)  (matches torch CosineSimilarity eps semantics)
// ---------------------------------------------------------------------------
__global__ void normalize_kernel(const float* __restrict__ x) {
    int row  = blockIdx.x * 8 + (threadIdx.x >> 5);
    int lane = threadIdx.x & 31;
    const float* xr = x + row * DDIM;
    float v0 = xr[lane];
    float v1 = xr[lane + 32];
    float s = v0 * v0 + v1 * v1;
    #pragma unroll
    for (int o = 16; o; o >>= 1) s += __shfl_xor_sync(0xffffffffu, s, o);
    float inv = 1.0f / fmaxf(sqrtf(s), EPS);
    g_xn[row * DDIM + lane]      = v0 * inv;
    g_xn[row * DDIM + lane + 32] = v1 * inv;
}

// ---------------------------------------------------------------------------
// Tiled Gram + loss reduction.
// 64x64 tile per block, upper triangle only (off-diagonal tiles weighted 2x).
// 256 threads as 16x16; each thread owns a 4x4 micro-tile with STRIDED
// mapping: i = ty + ii*16, j = tx + jj*16 -> conflict-free LDS.128 phases.
// Row stride 68 floats (16B aligned + bank rotation of 4 words/row).
// ---------------------------------------------------------------------------
__global__ __launch_bounds__(256) void loss_kernel(const int* __restrict__ cls) {
    const int bj = blockIdx.x;
    const int bi = blockIdx.y;
    if (bi > bj) return;

    __shared__ __align__(16) float As[64][68];
    __shared__ __align__(16) float Bs[64][68];
    __shared__ int ci_s[64];
    __shared__ int cj_s[64];
    __shared__ float red[8];

    const int tid = threadIdx.x;

    // Load tiles: 64 rows x 64 floats = 1024 float4 each; 4 per thread.
    const float4* Ag = (const float4*)(g_xn + (size_t)bi * 64 * DDIM);
    const float4* Bg = (const float4*)(g_xn + (size_t)bj * 64 * DDIM);
    #pragma unroll
    for (int r = 0; r < 4; r++) {
        int idx = tid + r * 256;     // [0,1024)
        int row = idx >> 4;          // 16 float4 per row
        int c   = (idx & 15) * 4;
        float4 a = Ag[idx];
        As[row][c + 0] = a.x; As[row][c + 1] = a.y;
        As[row][c + 2] = a.z; As[row][c + 3] = a.w;
        float4 b = Bg[idx];
        Bs[row][c + 0] = b.x; Bs[row][c + 1] = b.y;
        Bs[row][c + 2] = b.z; Bs[row][c + 3] = b.w;
    }
    if (tid < 64)                    ci_s[tid]      = cls[bi * 64 + tid];
    else if (tid < 128)              cj_s[tid - 64] = cls[bj * 64 + (tid - 64)];
    __syncthreads();

    const int ty = tid >> 4;
    const int tx = tid & 15;

    float acc[4][4];
    #pragma unroll
    for (int ii = 0; ii < 4; ii++)
        #pragma unroll
        for (int jj = 0; jj < 4; jj++) acc[ii][jj] = 0.0f;

    #pragma unroll
    for (int k = 0; k < DDIM; k += 4) {
        float4 a[4], b[4];
        #pragma unroll
        for (int ii = 0; ii < 4; ii++)
            a[ii] = *(const float4*)&As[ty + ii * 16][k];
        #pragma unroll
        for (int jj = 0; jj < 4; jj++)
            b[jj] = *(const float4*)&Bs[tx + jj * 16][k];
        #pragma unroll
        for (int ii = 0; ii < 4; ii++) {
            #pragma unroll
            for (int jj = 0; jj < 4; jj++) {
                acc[ii][jj] = fmaf(a[ii].x, b[jj].x, acc[ii][jj]);
                acc[ii][jj] = fmaf(a[ii].y, b[jj].y, acc[ii][jj]);
                acc[ii][jj] = fmaf(a[ii].z, b[jj].z, acc[ii][jj]);
                acc[ii][jj] = fmaf(a[ii].w, b[jj].w, acc[ii][jj]);
            }
        }
    }

    // Epilogue: loss[i,j] = same ? (1-cos) : relu(MARGIN - (1-cos))
    float lsum = 0.0f;
    #pragma unroll
    for (int ii = 0; ii < 4; ii++) {
        int ci = ci_s[ty + ii * 16];
        #pragma unroll
        for (int jj = 0; jj < 4; jj++) {
            int   cj   = cj_s[tx + jj * 16];
            float cosv = acc[ii][jj];
            float dist = 1.0f - cosv;
            float oth  = fmaxf(MARGIN - dist, 0.0f);
            lsum += (ci == cj) ? dist : oth;
        }
    }
    if (bi != bj) lsum *= 2.0f;   // symmetry: tile (bj,bi) counted here

    // Block reduction -> one double atomic per block.
    #pragma unroll
    for (int o = 16; o; o >>= 1) lsum += __shfl_xor_sync(0xffffffffu, lsum, o);
    if ((tid & 31) == 0) red[tid >> 5] = lsum;
    __syncthreads();
    if (tid == 0) {
        float t = 0.0f;
        #pragma unroll
        for (int w = 0; w < 8; w++) t += red[w];
        atomicAdd(&g_accum, (double)t);
    }
}

// ---------------------------------------------------------------------------
// Finalize: mean over N*N.
// ---------------------------------------------------------------------------
__global__ void finalize_kernel(float* __restrict__ out) {
    out[0] = (float)(g_accum / ((double)NROWS * (double)NROWS));
}

extern "C" void kernel_launch(void* const* d_in, const int* in_sizes, int n_in,
                              void* d_out, int out_size) {
    const float* bottleneck = (const float*)d_in[0];
    const int*   class_map  = (const int*)d_in[1];
    float*       out        = (float*)d_out;

    zero_kernel<<<1, 1>>>();
    normalize_kernel<<<NROWS / 8, 256>>>(bottleneck);
    dim3 grid(NROWS / 64, NROWS / 64);   // 128 x 128 tiles, lower half early-exits
    loss_kernel<<<grid, 256>>>(class_map);
    finalize_kernel<<<1, 1>>>(out);
}

// round 3
// speedup vs baseline: 3.9542x; 3.9542x over previous
#include <cuda_runtime.h>
#include <cuda_bf16.h>
#include <math.h>
#include <cstdint>

#define NROWS 8192
#define DDIM  64
#define MARGIN 1.1f
#define EPS 1e-8f
#define TILE 128
#define NTILES (NROWS / TILE)        // 64
#define ROWB  144                    // padded row stride in bytes (72 bf16)

// Scratch (no allocs allowed): normalized bf16 vectors + accumulator.
__device__ __align__(16) __nv_bfloat16 g_xb[NROWS * DDIM];
__device__ double g_accum;

__device__ __forceinline__ uint32_t smem_u32(const void* p) {
    uint32_t a;
    asm("{ .reg .u64 t; cvta.to.shared.u64 t, %1; cvt.u32.u64 %0, t; }"
        : "=r"(a) : "l"(p));
    return a;
}

__device__ __forceinline__ void ldsm_x4(uint32_t& r0, uint32_t& r1,
                                        uint32_t& r2, uint32_t& r3,
                                        uint32_t addr) {
    asm volatile("ldmatrix.sync.aligned.m8n8.x4.shared.b16 {%0,%1,%2,%3}, [%4];"
                 : "=r"(r0), "=r"(r1), "=r"(r2), "=r"(r3) : "r"(addr));
}

__device__ __forceinline__ void mma_16816(float* c, const uint32_t* a,
                                          uint32_t b0, uint32_t b1) {
    asm volatile(
        "mma.sync.aligned.m16n8k16.row.col.f32.bf16.bf16.f32 "
        "{%0,%1,%2,%3}, {%4,%5,%6,%7}, {%8,%9}, {%0,%1,%2,%3};"
        : "+f"(c[0]), "+f"(c[1]), "+f"(c[2]), "+f"(c[3])
        : "r"(a[0]), "r"(a[1]), "r"(a[2]), "r"(a[3]), "r"(b0), "r"(b1));
}

// ---------------------------------------------------------------------------
__global__ void zero_kernel() { g_accum = 0.0; }

// Normalize + convert to bf16. One warp per row.
__global__ void prep_kernel(const float* __restrict__ x) {
    int row  = blockIdx.x * 8 + (threadIdx.x >> 5);
    int lane = threadIdx.x & 31;
    const float* xr = x + row * DDIM;
    float v0 = xr[lane];
    float v1 = xr[lane + 32];
    float s = v0 * v0 + v1 * v1;
    #pragma unroll
    for (int o = 16; o; o >>= 1) s += __shfl_xor_sync(0xffffffffu, s, o);
    float inv = 1.0f / fmaxf(sqrtf(s), EPS);
    g_xb[row * DDIM + lane]      = __float2bfloat16(v0 * inv);
    g_xb[row * DDIM + lane + 32] = __float2bfloat16(v1 * inv);
}

// ---------------------------------------------------------------------------
// Tensor-core Gram tile + loss epilogue via mma.sync (HMMA).
// 128x128 tile per CTA, 256 threads = 8 warps, each warp owns 32x64.
// Upper-triangular tiles only; off-diagonal weighted 2x.
// ---------------------------------------------------------------------------
__global__ __launch_bounds__(256, 2) void gram_kernel(const int* __restrict__ cls) {
    const int bj = blockIdx.x;
    const int bi = blockIdx.y;
    if (bi > bj) return;

    __shared__ __align__(16) char As[TILE * ROWB];
    __shared__ __align__(16) char Bs_[TILE * ROWB];
    __shared__ int   csi[TILE];
    __shared__ int   csj[TILE];
    __shared__ float red[8];

    const int tid  = threadIdx.x;
    const int wid  = tid >> 5;
    const int lane = tid & 31;
    const bool diag = (bi == bj);

    // --- Load tiles: 128 rows x 128B, padded rows of 144B ---
    const uint4* Ag = (const uint4*)(g_xb + (size_t)bi * TILE * DDIM);
    #pragma unroll
    for (int r = 0; r < 4; r++) {
        int idx = tid + r * 256;        // [0,1024)
        int row = idx >> 3;
        int ch  = idx & 7;
        *(uint4*)(As + row * ROWB + ch * 16) = Ag[idx];
    }
    if (!diag) {
        const uint4* Bg = (const uint4*)(g_xb + (size_t)bj * TILE * DDIM);
        #pragma unroll
        for (int r = 0; r < 4; r++) {
            int idx = tid + r * 256;
            int row = idx >> 3;
            int ch  = idx & 7;
            *(uint4*)(Bs_ + row * ROWB + ch * 16) = Bg[idx];
        }
    }
    if (tid < TILE)      csi[tid]        = cls[bi * TILE + tid];
    else                 csj[tid - TILE] = cls[bj * TILE + (tid - TILE)];
    if (diag && tid >= TILE) csi[tid - TILE] = csj[tid - TILE];
    __syncthreads();

    const uint32_t a_base = smem_u32(As);
    const uint32_t b_base = diag ? a_base : smem_u32(Bs_);

    // Warp tiling: warp (wm, wn) owns rows wm*32..+32, cols wn*64..+64.
    const int wm = wid & 3;
    const int wn = wid >> 2;

    // ldmatrix per-lane addressing.
    // A (m16k16, x4): row = R + lane%16, byte = +((lane>>4)*16)
    const uint32_t a_lane_off =
        (uint32_t)((wm * 32 + (lane & 15)) * ROWB + ((lane >> 4) << 4));
    // B (two n8k16, x4): row = N + (lane&7) + ((lane>>4)<<3), byte = +(((lane>>3)&1)*16)
    const uint32_t b_lane_off =
        (uint32_t)((wn * 64 + (lane & 7) + ((lane >> 4) << 3)) * ROWB +
                   (((lane >> 3) & 1) << 4));

    float c[2][8][4];
    #pragma unroll
    for (int m = 0; m < 2; m++)
        #pragma unroll
        for (int n = 0; n < 8; n++)
            #pragma unroll
            for (int e = 0; e < 4; e++) c[m][n][e] = 0.0f;

    #pragma unroll
    for (int k = 0; k < 4; k++) {          // 4 k-steps of 16 bf16 (32B)
        uint32_t a[2][4];
        #pragma unroll
        for (int m = 0; m < 2; m++)
            ldsm_x4(a[m][0], a[m][1], a[m][2], a[m][3],
                    a_base + a_lane_off + m * 16 * ROWB + k * 32);

        uint32_t b[8][2];
        #pragma unroll
        for (int q = 0; q < 4; q++) {      // each x4 covers two n8 blocks
            uint32_t r0, r1, r2, r3;
            ldsm_x4(r0, r1, r2, r3,
                    b_base + b_lane_off + q * 16 * ROWB + k * 32);
            b[q * 2 + 0][0] = r0; b[q * 2 + 0][1] = r1;
            b[q * 2 + 1][0] = r2; b[q * 2 + 1][1] = r3;
        }

        #pragma unroll
        for (int m = 0; m < 2; m++)
            #pragma unroll
            for (int n = 0; n < 8; n++)
                mma_16816(c[m][n], a[m], b[n][0], b[n][1]);
    }

    // --- Epilogue: hinge loss on fragments ---
    // c[m][n][e]: row = wm*32 + m*16 + lane/4 + (e>=2 ? 8 : 0)
    //             col = wn*64 + n*8  + (lane%4)*2 + (e&1)
    const int quad = lane >> 2;
    const int tq   = lane & 3;
    float lsum = 0.0f;
    #pragma unroll
    for (int m = 0; m < 2; m++) {
        const int ci0 = csi[wm * 32 + m * 16 + quad];
        const int ci1 = csi[wm * 32 + m * 16 + quad + 8];
        #pragma unroll
        for (int n = 0; n < 8; n++) {
            const int colb = wn * 64 + n * 8 + tq * 2;
            const int cj0  = csj[colb];
            const int cj1  = csj[colb + 1];
            float d0 = 1.0f - c[m][n][0];
            float d1 = 1.0f - c[m][n][1];
            float d2 = 1.0f - c[m][n][2];
            float d3 = 1.0f - c[m][n][3];
            lsum += (ci0 == cj0) ? d0 : fmaxf(MARGIN - d0, 0.0f);
            lsum += (ci0 == cj1) ? d1 : fmaxf(MARGIN - d1, 0.0f);
            lsum += (ci1 == cj0) ? d2 : fmaxf(MARGIN - d2, 0.0f);
            lsum += (ci1 == cj1) ? d3 : fmaxf(MARGIN - d3, 0.0f);
        }
    }
    if (!diag) lsum *= 2.0f;     // symmetry: tile (bj,bi) accounted here

    // --- Block reduce -> one double atomic ---
    #pragma unroll
    for (int o = 16; o; o >>= 1) lsum += __shfl_xor_sync(0xffffffffu, lsum, o);
    if (lane == 0) red[wid] = lsum;
    __syncthreads();
    if (tid == 0) {
        float t = 0.0f;
        #pragma unroll
        for (int w = 0; w < 8; w++) t += red[w];
        atomicAdd(&g_accum, (double)t);
    }
}

__global__ void finalize_kernel(float* __restrict__ out) {
    out[0] = (float)(g_accum / ((double)NROWS * (double)NROWS));
}

extern "C" void kernel_launch(void* const* d_in, const int* in_sizes, int n_in,
                              void* d_out, int out_size) {
    const float* bottleneck = (const float*)d_in[0];
    const int*   class_map  = (const int*)d_in[1];
    float*       out        = (float*)d_out;

    zero_kernel<<<1, 1>>>();
    prep_kernel<<<NROWS / 8, 256>>>(bottleneck);
    dim3 grid(NTILES, NTILES);   // 64x64 tiles, lower half early-exits
    gram_kernel<<<grid, 256>>>(class_map);
    finalize_kernel<<<1, 1>>>(out);
}